// round 4
// baseline (speedup 1.0000x reference)
#include <cuda_runtime.h>
#include <math.h>

#define APAD 68            // padded row stride (floats) for activation matrix A^T[256][APAD]
#define EPSV 1e-6f

__device__ float g_latconst[256];   // b1 + latent @ W1[25:153]  (constant across batch)

// ---------------------------------------------------------------------------
// Precompute: lat_const[n] = b1[n] + sum_j emb[traj,j] * W1[25+j, n]
// ---------------------------------------------------------------------------
__global__ void latconst_kernel(const float* __restrict__ emb,
                                const int* __restrict__ traj,
                                const float* __restrict__ W1,
                                const float* __restrict__ b1) {
    int n = threadIdx.x;
    int tid = traj[0];
    const float* e = emb + (size_t)tid * 128;
    float s = b1[n];
#pragma unroll 4
    for (int j = 0; j < 128; ++j)
        s = fmaf(e[j], W1[(size_t)(25 + j) * 256 + n], s);
    g_latconst[n] = s;
}

__device__ __forceinline__ float gelu_f(float x) {
    // exact (erf) GELU, matches jax.nn.gelu(approximate=False)
    return 0.5f * x * (1.0f + erff(x * 0.7071067811865476f));
}

// ---------------------------------------------------------------------------
// One dense layer: out[64 x 256] = A[64 x K] @ W[K x 256] + binit ; optional GELU.
// A stored transposed in smem: A[k][m], row stride APAD.
// Thread t owns rows m0..m0+3 (m0 = (t>>4)*4) and cols n = (t&15) + 16*j.
// ---------------------------------------------------------------------------
__device__ __noinline__ void dense_layer(float* __restrict__ A,
                                         float* __restrict__ Wc,
                                         const float* __restrict__ Wg,
                                         const float* __restrict__ binit,
                                         int K, int t, bool act) {
    const int nblk = t & 15;
    const int mblk = t >> 4;
    float acc[4][16];
#pragma unroll
    for (int j = 0; j < 16; ++j) {
        float b = binit[nblk + 16 * j];
        acc[0][j] = b; acc[1][j] = b; acc[2][j] = b; acc[3][j] = b;
    }

    for (int kc = 0; kc < K; kc += 16) {
        int kk = min(16, K - kc);
        int nflt = kk * 256;
        // stage weight chunk (flat, contiguous in global) via float4
        for (int idx = t * 4; idx < nflt; idx += 1024)
            *(float4*)(Wc + idx) = *(const float4*)(Wg + (size_t)kc * 256 + idx);
        __syncthreads();

        if (kk == 16) {
#pragma unroll
            for (int k2 = 0; k2 < 16; ++k2) {
                float4 a = *(const float4*)(A + (kc + k2) * APAD + mblk * 4);
                const float* wr = Wc + k2 * 256 + nblk;
#pragma unroll
                for (int j = 0; j < 16; ++j) {
                    float w = wr[16 * j];
                    acc[0][j] = fmaf(a.x, w, acc[0][j]);
                    acc[1][j] = fmaf(a.y, w, acc[1][j]);
                    acc[2][j] = fmaf(a.z, w, acc[2][j]);
                    acc[3][j] = fmaf(a.w, w, acc[3][j]);
                }
            }
        } else {
            for (int k2 = 0; k2 < kk; ++k2) {
                float4 a = *(const float4*)(A + (kc + k2) * APAD + mblk * 4);
                const float* wr = Wc + k2 * 256 + nblk;
#pragma unroll
                for (int j = 0; j < 16; ++j) {
                    float w = wr[16 * j];
                    acc[0][j] = fmaf(a.x, w, acc[0][j]);
                    acc[1][j] = fmaf(a.y, w, acc[1][j]);
                    acc[2][j] = fmaf(a.z, w, acc[2][j]);
                    acc[3][j] = fmaf(a.w, w, acc[3][j]);
                }
            }
        }
        __syncthreads();   // all reads of A (and Wc) for this chunk done
    }

    // write outputs back into A (in place; safe after the trailing sync above)
#pragma unroll
    for (int j = 0; j < 16; ++j) {
        int n = nblk + 16 * j;
        float4 v;
        v.x = act ? gelu_f(acc[0][j]) : acc[0][j];
        v.y = act ? gelu_f(acc[1][j]) : acc[1][j];
        v.z = act ? gelu_f(acc[2][j]) : acc[2][j];
        v.w = act ? gelu_f(acc[3][j]) : acc[3][j];
        *(float4*)(A + n * APAD + mblk * 4) = v;
    }
    __syncthreads();
}

// ---------------------------------------------------------------------------
// Main kernel: 64 particles per CTA, 256 threads.
// ---------------------------------------------------------------------------
__global__ void __launch_bounds__(256, 2)
stress_kernel(const float* __restrict__ Fg, const float* __restrict__ Cg,
              const float* __restrict__ W1,
              const float* __restrict__ W2, const float* __restrict__ b2,
              const float* __restrict__ W3, const float* __restrict__ b3,
              const float* __restrict__ W4, const float* __restrict__ b4,
              const float* __restrict__ W5, const float* __restrict__ b5,
              float* __restrict__ outg, int B) {
    extern __shared__ float smem[];
    float* A  = smem;                 // 256 * APAD floats
    float* Wc = A + 256 * APAD;       // 16 * 256 floats (also stages W5: 2304 floats)
    float* Rb = Wc + 16 * 256;        // 64 * 9 floats (polar rotations)

    const int t = threadIdx.x;
    const int g0 = blockIdx.x * 64;

    // ---- Phase 1: per-particle features (threads 0..63, one particle each) ----
    if (t < 64) {
        int g = g0 + t;
        if (g < B) {
            const float* Fp = Fg + (size_t)g * 9;
            float F0 = Fp[0], F1 = Fp[1], F2 = Fp[2];
            float F3 = Fp[3], F4 = Fp[4], F5 = Fp[5];
            float F6 = Fp[6], F7 = Fp[7], F8 = Fp[8];

            const float* Cp = Cg + (size_t)g * 9;
#pragma unroll
            for (int i = 0; i < 9; ++i) A[(16 + i) * APAD + t] = Cp[i];

            // M = F^T F   (F row-major: F[k][i] = F(3k+i))
            float M00 = F0*F0 + F3*F3 + F6*F6;
            float M01 = F0*F1 + F3*F4 + F6*F7;
            float M02 = F0*F2 + F3*F5 + F6*F8;
            float M11 = F1*F1 + F4*F4 + F7*F7;
            float M12 = F1*F2 + F4*F5 + F7*F8;
            float M22 = F2*F2 + F5*F5 + F8*F8;

            float det = F0*(F4*F8 - F5*F7) - F1*(F3*F8 - F5*F6) + F2*(F3*F7 - F4*F6);

            // closed-form eigenvalues of symmetric M (sorted descending)
            float q  = (M00 + M11 + M22) * (1.0f / 3.0f);
            float p1 = M01*M01 + M02*M02 + M12*M12;
            float d0 = M00 - q, d1 = M11 - q, d2 = M22 - q;
            float p2 = d0*d0 + d1*d1 + d2*d2 + 2.0f*p1;
            float p  = sqrtf(p2 * (1.0f / 6.0f) + 1e-30f);
            float ip = 1.0f / p;
            float B00 = d0*ip, B01 = M01*ip, B02 = M02*ip;
            float B11 = d1*ip, B12 = M12*ip, B22 = d2*ip;
            float detB = B00*(B11*B22 - B12*B12)
                       - B01*(B01*B22 - B12*B02)
                       + B02*(B01*B12 - B11*B02);
            float r = fminf(1.0f, fmaxf(-1.0f, 0.5f * detB));
            float phi = acosf(r) * (1.0f / 3.0f);
            float e1 = q + 2.0f * p * cosf(phi);
            float e3 = q + 2.0f * p * cosf(phi + 2.0943951023931953f);
            float e2 = 3.0f * q - e1 - e3;
            float s0 = sqrtf(fmaxf(e1, 0.0f));
            float s1 = sqrtf(fmaxf(e2, 0.0f));
            float s2 = sqrtf(fmaxf(e3, 0.0f));

            A[0*APAD + t] = s0 - 1.0f;
            A[1*APAD + t] = s1 - 1.0f;
            A[2*APAD + t] = s2 - 1.0f;
            A[3*APAD + t]  = M00 - 1.0f;
            A[4*APAD + t]  = M01;
            A[5*APAD + t]  = M02;
            A[6*APAD + t]  = M01;
            A[7*APAD + t]  = M11 - 1.0f;
            A[8*APAD + t]  = M12;
            A[9*APAD + t]  = M02;
            A[10*APAD + t] = M12;
            A[11*APAD + t] = M22 - 1.0f;
            A[12*APAD + t] = det - 1.0f;
            A[13*APAD + t] = logf(det) - 1.0f;
            float f00 = fmaxf(F0, EPSV);
            A[14*APAD + t] = f00 - 1.0f;
            A[15*APAD + t] = logf(f00) - 1.0f;

            // polar rotation R via Newton iteration X <- 0.5 (X + X^-T)
            float X0=F0, X1=F1, X2=F2, X3=F3, X4=F4, X5=F5, X6=F6, X7=F7, X8=F8;
#pragma unroll
            for (int it = 0; it < 4; ++it) {
                float C00 =   X4*X8 - X5*X7;
                float C01 = -(X3*X8 - X5*X6);
                float C02 =   X3*X7 - X4*X6;
                float C10 = -(X1*X8 - X2*X7);
                float C11 =   X0*X8 - X2*X6;
                float C12 = -(X0*X7 - X1*X6);
                float C20 =   X1*X5 - X2*X4;
                float C21 = -(X0*X5 - X2*X3);
                float C22 =   X0*X4 - X1*X3;
                float dX  = X0*C00 + X1*C01 + X2*C02;
                float h   = 0.5f / dX;     // cofactor/det = X^-T
                X0 = 0.5f*X0 + C00*h; X1 = 0.5f*X1 + C01*h; X2 = 0.5f*X2 + C02*h;
                X3 = 0.5f*X3 + C10*h; X4 = 0.5f*X4 + C11*h; X5 = 0.5f*X5 + C12*h;
                X6 = 0.5f*X6 + C20*h; X7 = 0.5f*X7 + C21*h; X8 = 0.5f*X8 + C22*h;
            }
            Rb[t*9+0]=X0; Rb[t*9+1]=X1; Rb[t*9+2]=X2;
            Rb[t*9+3]=X3; Rb[t*9+4]=X4; Rb[t*9+5]=X5;
            Rb[t*9+6]=X6; Rb[t*9+7]=X7; Rb[t*9+8]=X8;
        } else {
            for (int k = 0; k < 25; ++k) A[k*APAD + t] = 0.0f;
        }
    }
    __syncthreads();

    // ---- Phase 2: MLP ----
    dense_layer(A, Wc, W1, g_latconst, 25, t, true);   // layer 1 (latent folded into bias)
    {
        const float* Ws[3] = {W2, W3, W4};
        const float* bs[3] = {b2, b3, b4};
#pragma unroll 1
        for (int L = 0; L < 3; ++L)
            dense_layer(A, Wc, Ws[L], bs[L], 256, t, true);
    }

    // ---- Layer 5 (256 -> 9) + epilogue ----
    for (int idx = t; idx < 576; idx += 256)            // stage W5 (2304 floats)
        ((float4*)Wc)[idx] = ((const float4*)W5)[idx];
    __syncthreads();

    if (t < 64) {
        int g = g0 + t;
        if (g < B) {
            float o[9];
#pragma unroll
            for (int j = 0; j < 9; ++j) o[j] = b5[j];
#pragma unroll 4
            for (int k = 0; k < 256; ++k) {
                float a = A[k*APAD + t];
                const float* wr = Wc + k * 9;
#pragma unroll
                for (int j = 0; j < 9; ++j) o[j] = fmaf(a, wr[j], o[j]);
            }
            // symmetrize
            float x00 = o[0], x11 = o[4], x22 = o[8];
            float x01 = 0.5f * (o[1] + o[3]);
            float x02 = 0.5f * (o[2] + o[6]);
            float x12 = 0.5f * (o[5] + o[7]);

            float R0=Rb[t*9+0], R1=Rb[t*9+1], R2=Rb[t*9+2];
            float R3=Rb[t*9+3], R4=Rb[t*9+4], R5=Rb[t*9+5];
            float R6=Rb[t*9+6], R7=Rb[t*9+7], R8=Rb[t*9+8];

            // P = R @ sym(x)
            float P00 = R0*x00 + R1*x01 + R2*x02;
            float P01 = R0*x01 + R1*x11 + R2*x12;
            float P02 = R0*x02 + R1*x12 + R2*x22;
            float P10 = R3*x00 + R4*x01 + R5*x02;
            float P11 = R3*x01 + R4*x11 + R5*x12;
            float P12 = R3*x02 + R4*x12 + R5*x22;
            float P20 = R6*x00 + R7*x01 + R8*x02;
            float P21 = R6*x01 + R7*x11 + R8*x12;
            float P22 = R6*x02 + R7*x12 + R8*x22;

            const float* Fp = Fg + (size_t)g * 9;
            float F0 = Fp[0], F1 = Fp[1], F2 = Fp[2];
            float F3 = Fp[3], F4 = Fp[4], F5 = Fp[5];
            float F6 = Fp[6], F7 = Fp[7], F8 = Fp[8];

            // cauchy = P @ F^T  :  c[i][j] = sum_k P[i][k] * F[j][k]
            float* op = outg + (size_t)g * 9;
            op[0] = P00*F0 + P01*F1 + P02*F2;
            op[1] = P00*F3 + P01*F4 + P02*F5;
            op[2] = P00*F6 + P01*F7 + P02*F8;
            op[3] = P10*F0 + P11*F1 + P12*F2;
            op[4] = P10*F3 + P11*F4 + P12*F5;
            op[5] = P10*F6 + P11*F7 + P12*F8;
            op[6] = P20*F0 + P21*F1 + P22*F2;
            op[7] = P20*F3 + P21*F4 + P22*F5;
            op[8] = P20*F6 + P21*F7 + P22*F8;
        }
    }
}

// ---------------------------------------------------------------------------
extern "C" void kernel_launch(void* const* d_in, const int* in_sizes, int n_in,
                              void* d_out, int out_size) {
    const float* F    = (const float*)d_in[0];
    const float* C    = (const float*)d_in[1];
    const float* emb  = (const float*)d_in[2];
    const int*   traj = (const int*)d_in[3];
    const float* W1 = (const float*)d_in[4];
    const float* b1 = (const float*)d_in[5];
    const float* W2 = (const float*)d_in[6];
    const float* b2 = (const float*)d_in[7];
    const float* W3 = (const float*)d_in[8];
    const float* b3 = (const float*)d_in[9];
    const float* W4 = (const float*)d_in[10];
    const float* b4 = (const float*)d_in[11];
    const float* W5 = (const float*)d_in[12];
    const float* b5 = (const float*)d_in[13];

    int B = in_sizes[0] / 9;

    latconst_kernel<<<1, 256>>>(emb, traj, W1, b1);

    size_t smem = (size_t)(256 * APAD + 16 * 256 + 64 * 9) * sizeof(float);
    cudaFuncSetAttribute(stress_kernel, cudaFuncAttributeMaxDynamicSharedMemorySize, (int)smem);

    int grid = (B + 63) / 64;
    stress_kernel<<<grid, 256, smem>>>(F, C, W1, W2, b2, W3, b3, W4, b4, W5, b5,
                                       (float*)d_out, B);
}